// round 10
// baseline (speedup 1.0000x reference)
#include <cuda_runtime.h>
#include <math.h>
#include <stdint.h>

#define NB 64
#define NPG 2048
#define NC 64
#define NH 4
#define ND 64
#define SPLIT 4
#define TILE 128
#define KV_TILES ((NPG / SPLIT) / TILE)   // 4
#define NPART (SPLIT * 2)                 // 8 kv partials (2 halves per block)
#define NTH 128

// ---------------- device scratch ----------------
__device__ float g_kv_part[NB * NH * NPART * ND * NC];
__device__ float g_kv[NB * NH * ND * NC];
__device__ float g_ksum_part[NB * NH * SPLIT * ND];
__device__ float g_ksum[NB * NH * ND];
__device__ float g_vsum[NB * NC];

// ---------------- f32x2 helpers ----------------
__device__ __forceinline__ uint64_t pack2(float lo, float hi) {
    uint64_t r; asm("mov.b64 %0, {%1,%2};" : "=l"(r) : "f"(lo), "f"(hi)); return r;
}
__device__ __forceinline__ float2 unpack2(uint64_t v) {
    float2 r; asm("mov.b64 {%0,%1}, %2;" : "=f"(r.x), "=f"(r.y) : "l"(v)); return r;
}
__device__ __forceinline__ void ffma2(uint64_t& d, uint64_t a, uint64_t b) {
    asm("fma.rn.f32x2 %0, %1, %2, %0;" : "+l"(d) : "l"(a), "l"(b));
}

// ---------------- smem layouts ----------------
struct alignas(16) SmemKV {
    float Xs[TILE][NC + 4];   // node tile, c contiguous
    float Ks[TILE][ND + 4];   // normalized K, d contiguous
    float Wt[NC][ND];         // W transposed: [c][d]
    float red[TILE][9];
    float red2[ND][17];       // ksum partials [d][ti]
    float invn[TILE];
    float ksum_s[ND];
    float bks[ND];
};

struct alignas(16) SmemOut {
    float Xs[TILE][NC + 4];
    float Qs[TILE][ND + 4];   // raw Q, d contiguous
    float Wt[NC][ND];
    float kvs[ND][NC];
    float red1[TILE][9];
    float red2[TILE][9];
    float scale[TILE];
    float invden[TILE];
    float ksum[ND];
    float vsum[NC];
    float bqs[ND];
};

// ---------------- vsum ----------------
__global__ __launch_bounds__(256) void vsum_kernel(const float* __restrict__ x) {
    __shared__ float sh[4][64];
    const int b = blockIdx.x;
    const int t = threadIdx.x;
    const int c = t & 63, s = t >> 6;
    const float* xb = x + (size_t)b * NPG * NC;
    float acc = 0.f;
    for (int n = s; n < NPG; n += 4) acc += xb[(size_t)n * NC + c];
    sh[s][c] = acc;
    __syncthreads();
    if (t < 64) g_vsum[b * NC + t] = sh[0][t] + sh[1][t] + sh[2][t] + sh[3][t];
}

// ---------------- K path ----------------
__global__ __launch_bounds__(NTH) void kv_kernel(
    const float* __restrict__ x,
    const float* __restrict__ Wk_w,
    const float* __restrict__ Wk_b)
{
    extern __shared__ char sraw[];
    SmemKV& s = *reinterpret_cast<SmemKV*>(sraw);
    const int split = blockIdx.x, h = blockIdx.y, b = blockIdx.z;
    const int tid = threadIdx.x;
    const int ti = tid >> 3, tj = tid & 7;
    const int i0 = ti * 8, j0 = tj * 8;
    const int half = tid >> 6, tid2 = tid & 63;
    const int d0 = (tid2 >> 3) * 8, c0 = (tid2 & 7) * 8;

    // stage transposed weights (conflict-free: bank = d mod 32) + bias
    {
        const int d = tid & 63, cg = tid >> 6;
        const float* wrow = Wk_w + (size_t)(h * ND + d) * NC + cg * 32;
        #pragma unroll
        for (int k = 0; k < 8; k++) {
            float4 w4 = *(const float4*)(wrow + k * 4);
            int c = cg * 32 + k * 4;
            s.Wt[c + 0][d] = w4.x; s.Wt[c + 1][d] = w4.y;
            s.Wt[c + 2][d] = w4.z; s.Wt[c + 3][d] = w4.w;
        }
        if (tid < ND) { s.bks[tid] = Wk_b[h * ND + tid]; s.ksum_s[tid] = 0.f; }
    }
    __syncthreads();

    uint64_t binit[4];
    #pragma unroll
    for (int e2 = 0; e2 < 4; e2++)
        binit[e2] = pack2(s.bks[j0 + 2 * e2], s.bks[j0 + 2 * e2 + 1]);

    uint64_t kvacc[8][4];
    #pragma unroll
    for (int a = 0; a < 8; a++)
        #pragma unroll
        for (int e2 = 0; e2 < 4; e2++) kvacc[a][e2] = 0ull;

    const int node0 = b * NPG + split * (NPG / SPLIT);

    for (int t = 0; t < KV_TILES; t++) {
        __syncthreads();
        // stage X tile (coalesced)
        {
            const float* xt = x + (size_t)(node0 + t * TILE) * NC;
            #pragma unroll
            for (int k = 0; k < 16; k++) {
                int g = tid + k * NTH;           // float4 index
                int row = g >> 4, c4 = g & 15;
                *(float4*)(&s.Xs[row][c4 * 4]) = *(const float4*)(xt + row * NC + c4 * 4);
            }
        }
        __syncthreads();

        // ---- proj: K[i][d] = X[i][:].Wk[d][:] + b ----
        uint64_t acc[8][4];
        #pragma unroll
        for (int a = 0; a < 8; a++)
            #pragma unroll
            for (int e2 = 0; e2 < 4; e2++) acc[a][e2] = binit[e2];

        #pragma unroll 2
        for (int c4 = 0; c4 < 16; c4++) {
            float4 x4[8];
            #pragma unroll
            for (int a = 0; a < 8; a++) x4[a] = *(const float4*)(&s.Xs[i0 + a][c4 * 4]);
            #pragma unroll
            for (int k = 0; k < 4; k++) {
                const int c = c4 * 4 + k;
                ulonglong2 w01 = *(const ulonglong2*)(&s.Wt[c][j0]);
                ulonglong2 w23 = *(const ulonglong2*)(&s.Wt[c][j0 + 4]);
                #pragma unroll
                for (int a = 0; a < 8; a++) {
                    float xs = (k == 0) ? x4[a].x : (k == 1) ? x4[a].y : (k == 2) ? x4[a].z : x4[a].w;
                    uint64_t xd = pack2(xs, xs);
                    ffma2(acc[a][0], xd, w01.x);
                    ffma2(acc[a][1], xd, w01.y);
                    ffma2(acc[a][2], xd, w23.x);
                    ffma2(acc[a][3], xd, w23.y);
                }
            }
        }

        // ---- normalize (deterministic staged reduction) ----
        float f[8][8];
        #pragma unroll
        for (int a = 0; a < 8; a++) {
            float sq = 0.f;
            #pragma unroll
            for (int e2 = 0; e2 < 4; e2++) {
                float2 v = unpack2(acc[a][e2]);
                f[a][2 * e2] = v.x; f[a][2 * e2 + 1] = v.y;
                sq += v.x * v.x + v.y * v.y;
            }
            s.red[i0 + a][tj] = sq;
        }
        __syncthreads();
        {
            float sq = 0.f;
            #pragma unroll
            for (int j = 0; j < 8; j++) sq += s.red[tid][j];
            s.invn[tid] = rsqrtf(sq);
        }
        __syncthreads();
        {
            float kspart[8];
            #pragma unroll
            for (int e = 0; e < 8; e++) kspart[e] = 0.f;
            #pragma unroll
            for (int a = 0; a < 8; a++) {
                const float sc = s.invn[i0 + a];
                float kp[8];
                #pragma unroll
                for (int e = 0; e < 8; e++) { kp[e] = f[a][e] * sc; kspart[e] += kp[e]; }
                *(float4*)(&s.Ks[i0 + a][j0])     = make_float4(kp[0], kp[1], kp[2], kp[3]);
                *(float4*)(&s.Ks[i0 + a][j0 + 4]) = make_float4(kp[4], kp[5], kp[6], kp[7]);
            }
            #pragma unroll
            for (int e = 0; e < 8; e++) s.red2[j0 + e][ti] = kspart[e];
        }
        __syncthreads();
        if (tid < ND) {
            float v = 0.f;
            #pragma unroll
            for (int g = 0; g < 16; g++) v += s.red2[tid][g];
            s.ksum_s[tid] += v;
        }

        // ---- kv[d][c] += sum_i Kn[i][d] * X[i][c]  (halves split the i range) ----
        #pragma unroll 1
        for (int i = 0; i < 64; i++) {
            const int ii = half * 64 + i;
            float4 ka = *(const float4*)(&s.Ks[ii][d0]);
            float4 kb = *(const float4*)(&s.Ks[ii][d0 + 4]);
            ulonglong2 xv01 = *(const ulonglong2*)(&s.Xs[ii][c0]);
            ulonglong2 xv23 = *(const ulonglong2*)(&s.Xs[ii][c0 + 4]);
            float kd[8] = {ka.x, ka.y, ka.z, ka.w, kb.x, kb.y, kb.z, kb.w};
            #pragma unroll
            for (int a = 0; a < 8; a++) {
                uint64_t k2 = pack2(kd[a], kd[a]);
                ffma2(kvacc[a][0], k2, xv01.x);
                ffma2(kvacc[a][1], k2, xv01.y);
                ffma2(kvacc[a][2], k2, xv23.x);
                ffma2(kvacc[a][3], k2, xv23.y);
            }
        }
    }
    __syncthreads();

    // write partials
    {
        const int p = split * 2 + half;
        float* dst = g_kv_part + (((size_t)(b * NH + h) * NPART + p) * ND + d0) * NC + c0;
        #pragma unroll
        for (int a = 0; a < 8; a++) {
            float2 v0 = unpack2(kvacc[a][0]), v1 = unpack2(kvacc[a][1]);
            float2 v2 = unpack2(kvacc[a][2]), v3 = unpack2(kvacc[a][3]);
            *(float4*)(dst + a * NC)     = make_float4(v0.x, v0.y, v1.x, v1.y);
            *(float4*)(dst + a * NC + 4) = make_float4(v2.x, v2.y, v3.x, v3.y);
        }
    }
    if (tid < ND)
        g_ksum_part[((size_t)(b * NH + h) * SPLIT + split) * ND + tid] = s.ksum_s[tid];
}

// ---------------- reduce split partials ----------------
__global__ __launch_bounds__(256) void reduce_kernel() {
    const int KV = NB * NH * ND * NC;
    const int KS = NB * NH * ND;
    int idx = blockIdx.x * 256 + threadIdx.x;
    if (idx < KV) {
        int bh = idx / (ND * NC), rem = idx % (ND * NC);
        float sum = 0.f;
        #pragma unroll
        for (int sp = 0; sp < NPART; sp++)
            sum += g_kv_part[((size_t)bh * NPART + sp) * (ND * NC) + rem];
        g_kv[idx] = sum;
    } else if (idx < KV + KS) {
        int j = idx - KV;
        int bh = j / ND, rem = j % ND;
        float sum = 0.f;
        #pragma unroll
        for (int sp = 0; sp < SPLIT; sp++)
            sum += g_ksum_part[((size_t)bh * SPLIT + sp) * ND + rem];
        g_ksum[j] = sum;
    }
}

// ---------------- Q path + output ----------------
__global__ __launch_bounds__(NTH) void out_kernel(
    const float* __restrict__ x,
    const float* __restrict__ Wq_w,
    const float* __restrict__ Wq_b,
    const int* __restrict__ n_nodes,
    float* __restrict__ out)
{
    extern __shared__ char sraw[];
    SmemOut& s = *reinterpret_cast<SmemOut*>(sraw);
    const int t = blockIdx.x, b = blockIdx.y;
    const int tid = threadIdx.x;
    const int ti = tid >> 3, tj = tid & 7;
    const int i0 = ti * 8, j0 = tj * 8;
    const float nn = (float)n_nodes[b];

    // stage X tile + vsum (once per block)
    {
        const float* xt = x + (size_t)(b * NPG + t * TILE) * NC;
        #pragma unroll
        for (int k = 0; k < 16; k++) {
            int g = tid + k * NTH;
            int row = g >> 4, c4 = g & 15;
            *(float4*)(&s.Xs[row][c4 * 4]) = *(const float4*)(xt + row * NC + c4 * 4);
        }
        if (tid < NC) s.vsum[tid] = g_vsum[b * NC + tid];
    }

    for (int h = 0; h < NH; h++) {
        __syncthreads();  // protects Wt/kvs reuse + initial staging
        {
            const int d = tid & 63, cg = tid >> 6;
            const float* wrow = Wq_w + (size_t)(h * ND + d) * NC + cg * 32;
            #pragma unroll
            for (int k = 0; k < 8; k++) {
                float4 w4 = *(const float4*)(wrow + k * 4);
                int c = cg * 32 + k * 4;
                s.Wt[c + 0][d] = w4.x; s.Wt[c + 1][d] = w4.y;
                s.Wt[c + 2][d] = w4.z; s.Wt[c + 3][d] = w4.w;
            }
            const float4* kvsrc = (const float4*)(g_kv + (size_t)(b * NH + h) * (ND * NC));
            float4* kvdst = (float4*)(&s.kvs[0][0]);
            #pragma unroll
            for (int k = 0; k < 8; k++) kvdst[tid + k * NTH] = kvsrc[tid + k * NTH];
            if (tid < ND) {
                s.bqs[tid] = Wq_b[h * ND + tid];
                s.ksum[tid] = g_ksum[(size_t)(b * NH + h) * ND + tid];
            }
        }
        __syncthreads();

        // ---- GEMM1: Qraw = X.Wq^T + b ----
        uint64_t acc[8][4];
        {
            uint64_t binit[4];
            #pragma unroll
            for (int e2 = 0; e2 < 4; e2++)
                binit[e2] = pack2(s.bqs[j0 + 2 * e2], s.bqs[j0 + 2 * e2 + 1]);
            #pragma unroll
            for (int a = 0; a < 8; a++)
                #pragma unroll
                for (int e2 = 0; e2 < 4; e2++) acc[a][e2] = binit[e2];
        }
        #pragma unroll 2
        for (int c4 = 0; c4 < 16; c4++) {
            float4 x4[8];
            #pragma unroll
            for (int a = 0; a < 8; a++) x4[a] = *(const float4*)(&s.Xs[i0 + a][c4 * 4]);
            #pragma unroll
            for (int k = 0; k < 4; k++) {
                const int c = c4 * 4 + k;
                ulonglong2 w01 = *(const ulonglong2*)(&s.Wt[c][j0]);
                ulonglong2 w23 = *(const ulonglong2*)(&s.Wt[c][j0 + 4]);
                #pragma unroll
                for (int a = 0; a < 8; a++) {
                    float xs = (k == 0) ? x4[a].x : (k == 1) ? x4[a].y : (k == 2) ? x4[a].z : x4[a].w;
                    uint64_t xd = pack2(xs, xs);
                    ffma2(acc[a][0], xd, w01.x);
                    ffma2(acc[a][1], xd, w01.y);
                    ffma2(acc[a][2], xd, w23.x);
                    ffma2(acc[a][3], xd, w23.y);
                }
            }
        }

        // ---- reductions: sumsq(q), dot(q, ksum); store raw Q ----
        #pragma unroll
        for (int a = 0; a < 8; a++) {
            float f[8];
            float sq = 0.f, dk = 0.f;
            #pragma unroll
            for (int e2 = 0; e2 < 4; e2++) {
                float2 v = unpack2(acc[a][e2]);
                f[2 * e2] = v.x; f[2 * e2 + 1] = v.y;
            }
            #pragma unroll
            for (int e = 0; e < 8; e++) {
                sq += f[e] * f[e];
                dk += f[e] * s.ksum[j0 + e];
            }
            s.red1[i0 + a][tj] = sq;
            s.red2[i0 + a][tj] = dk;
            *(float4*)(&s.Qs[i0 + a][j0])     = make_float4(f[0], f[1], f[2], f[3]);
            *(float4*)(&s.Qs[i0 + a][j0 + 4]) = make_float4(f[4], f[5], f[6], f[7]);
        }
        __syncthreads();
        {
            float sq = 0.f, dk = 0.f;
            #pragma unroll
            for (int j = 0; j < 8; j++) { sq += s.red1[tid][j]; dk += s.red2[tid][j]; }
            float sc = rsqrtf(sq);
            s.scale[tid] = sc;
            s.invden[tid] = 1.0f / (sc * dk + nn);
        }
        __syncthreads();

        // ---- GEMM2: r = Qraw . kv ----
        uint64_t r2[8][4];
        #pragma unroll
        for (int a = 0; a < 8; a++)
            #pragma unroll
            for (int e2 = 0; e2 < 4; e2++) r2[a][e2] = 0ull;

        #pragma unroll 2
        for (int d4 = 0; d4 < 16; d4++) {
            float4 q4[8];
            #pragma unroll
            for (int a = 0; a < 8; a++) q4[a] = *(const float4*)(&s.Qs[i0 + a][d4 * 4]);
            #pragma unroll
            for (int k = 0; k < 4; k++) {
                const int d = d4 * 4 + k;
                ulonglong2 kv01 = *(const ulonglong2*)(&s.kvs[d][j0]);
                ulonglong2 kv23 = *(const ulonglong2*)(&s.kvs[d][j0 + 4]);
                #pragma unroll
                for (int a = 0; a < 8; a++) {
                    float qs = (k == 0) ? q4[a].x : (k == 1) ? q4[a].y : (k == 2) ? q4[a].z : q4[a].w;
                    uint64_t qd = pack2(qs, qs);
                    ffma2(r2[a][0], qd, kv01.x);
                    ffma2(r2[a][1], qd, kv01.y);
                    ffma2(r2[a][2], qd, kv23.x);
                    ffma2(r2[a][3], qd, kv23.y);
                }
            }
        }

        // ---- epilogue ----
        #pragma unroll
        for (int a = 0; a < 8; a++) {
            const float sc  = s.scale[i0 + a];
            const float idn = s.invden[i0 + a];
            float2 v0 = unpack2(r2[a][0]), v1 = unpack2(r2[a][1]);
            float2 v2 = unpack2(r2[a][2]), v3 = unpack2(r2[a][3]);
            float rr[8] = {v0.x, v0.y, v1.x, v1.y, v2.x, v2.y, v3.x, v3.y};
            float o[8];
            #pragma unroll
            for (int e = 0; e < 8; e++)
                o[e] = (sc * rr[e] + s.vsum[j0 + e]) * idn;
            float* orow = out + (size_t)(b * NPG + t * TILE + i0 + a) * (NH * NC) + h * NC + j0;
            *(float4*)(orow)     = make_float4(o[0], o[1], o[2], o[3]);
            *(float4*)(orow + 4) = make_float4(o[4], o[5], o[6], o[7]);
        }
    }
}

// ---------------- launch ----------------
extern "C" void kernel_launch(void* const* d_in, const int* in_sizes, int n_in,
                              void* d_out, int out_size) {
    const float* x    = (const float*)d_in[0];
    const float* Wq_w = (const float*)d_in[1];
    const float* Wq_b = (const float*)d_in[2];
    const float* Wk_w = (const float*)d_in[3];
    const float* Wk_b = (const float*)d_in[4];
    const int*   n_nodes = (const int*)d_in[5];
    float* out = (float*)d_out;

    cudaFuncSetAttribute(kv_kernel, cudaFuncAttributeMaxDynamicSharedMemorySize,
                         (int)sizeof(SmemKV));
    cudaFuncSetAttribute(out_kernel, cudaFuncAttributeMaxDynamicSharedMemorySize,
                         (int)sizeof(SmemOut));

    vsum_kernel<<<NB, 256>>>(x);
    kv_kernel<<<dim3(SPLIT, NH, NB), NTH, sizeof(SmemKV)>>>(x, Wk_w, Wk_b);

    const int total = NB * NH * ND * NC + NB * NH * ND;
    reduce_kernel<<<(total + 255) / 256, 256>>>();

    out_kernel<<<dim3(NPG / TILE, NB), NTH, sizeof(SmemOut)>>>(x, Wq_w, Wq_b, n_nodes, out);
}

// round 11
// speedup vs baseline: 1.0026x; 1.0026x over previous
#include <cuda_runtime.h>
#include <math.h>
#include <stdint.h>

#define NB 64
#define NPG 2048
#define NC 64
#define NH 4
#define ND 64
#define SPLIT 4
#define TILE 128
#define KV_TILES ((NPG / SPLIT) / TILE)   // 4
#define NPART (SPLIT * 2)                 // 8 kv partials (2 halves per block)
#define NTH 128

// ---------------- device scratch ----------------
__device__ float g_kv_part[NB * NH * NPART * ND * NC];
__device__ float g_kv[NB * NH * ND * NC];
__device__ float g_ksum_part[NB * NH * SPLIT * ND];
__device__ float g_ksum[NB * NH * ND];
__device__ float g_vsum[NB * NC];

// ---------------- f32x2 helpers ----------------
__device__ __forceinline__ uint64_t pack2(float lo, float hi) {
    uint64_t r; asm("mov.b64 %0, {%1,%2};" : "=l"(r) : "f"(lo), "f"(hi)); return r;
}
__device__ __forceinline__ float2 unpack2(uint64_t v) {
    float2 r; asm("mov.b64 {%0,%1}, %2;" : "=f"(r.x), "=f"(r.y) : "l"(v)); return r;
}
__device__ __forceinline__ void ffma2(uint64_t& d, uint64_t a, uint64_t b) {
    asm("fma.rn.f32x2 %0, %1, %2, %0;" : "+l"(d) : "l"(a), "l"(b));
}

// ---------------- smem layouts ----------------
struct alignas(16) SmemKV {
    float Xs[TILE][NC + 4];   // node tile, c contiguous
    float Ks[TILE][ND + 4];   // normalized K, d contiguous
    float Wt[NC][ND];         // W transposed: [c][d]
    float red[TILE][9];
    float red2[ND][17];       // ksum partials [d][ti]
    float invn[TILE];
    float ksum_s[ND];
    float bks[ND];
};

struct alignas(16) SmemOut {
    float Xs[TILE][NC + 4];
    float Qs[TILE][ND + 4];   // raw Q, d contiguous
    float Wt[NC][ND];
    float kvs[ND][NC];
    float red1[TILE][9];
    float red2[TILE][9];
    float scale[TILE];
    float invden[TILE];
    float ksum[ND];
    float vsum[NC];
    float bqs[ND];
};

// ---------------- vsum ----------------
__global__ __launch_bounds__(256) void vsum_kernel(const float* __restrict__ x) {
    __shared__ float sh[4][64];
    const int b = blockIdx.x;
    const int t = threadIdx.x;
    const int c = t & 63, s = t >> 6;
    const float* xb = x + (size_t)b * NPG * NC;
    float acc = 0.f;
    for (int n = s; n < NPG; n += 4) acc += xb[(size_t)n * NC + c];
    sh[s][c] = acc;
    __syncthreads();
    if (t < 64) g_vsum[b * NC + t] = sh[0][t] + sh[1][t] + sh[2][t] + sh[3][t];
}

// ---------------- K path ----------------
__global__ __launch_bounds__(NTH) void kv_kernel(
    const float* __restrict__ x,
    const float* __restrict__ Wk_w,
    const float* __restrict__ Wk_b)
{
    extern __shared__ char sraw[];
    SmemKV& s = *reinterpret_cast<SmemKV*>(sraw);
    const int split = blockIdx.x, h = blockIdx.y, b = blockIdx.z;
    const int tid = threadIdx.x;
    const int ti = tid >> 3, tj = tid & 7;
    const int i0 = ti * 8, j0 = tj * 8;
    const int half = tid >> 6, tid2 = tid & 63;
    const int d0 = (tid2 >> 3) * 8, c0 = (tid2 & 7) * 8;

    // stage transposed weights (conflict-free: bank = d mod 32) + bias
    {
        const int d = tid & 63, cg = tid >> 6;
        const float* wrow = Wk_w + (size_t)(h * ND + d) * NC + cg * 32;
        #pragma unroll
        for (int k = 0; k < 8; k++) {
            float4 w4 = *(const float4*)(wrow + k * 4);
            int c = cg * 32 + k * 4;
            s.Wt[c + 0][d] = w4.x; s.Wt[c + 1][d] = w4.y;
            s.Wt[c + 2][d] = w4.z; s.Wt[c + 3][d] = w4.w;
        }
        if (tid < ND) { s.bks[tid] = Wk_b[h * ND + tid]; s.ksum_s[tid] = 0.f; }
    }
    __syncthreads();

    uint64_t binit[4];
    #pragma unroll
    for (int e2 = 0; e2 < 4; e2++)
        binit[e2] = pack2(s.bks[j0 + 2 * e2], s.bks[j0 + 2 * e2 + 1]);

    uint64_t kvacc[8][4];
    #pragma unroll
    for (int a = 0; a < 8; a++)
        #pragma unroll
        for (int e2 = 0; e2 < 4; e2++) kvacc[a][e2] = 0ull;

    const int node0 = b * NPG + split * (NPG / SPLIT);

    for (int t = 0; t < KV_TILES; t++) {
        __syncthreads();
        // stage X tile (coalesced)
        {
            const float* xt = x + (size_t)(node0 + t * TILE) * NC;
            #pragma unroll
            for (int k = 0; k < 16; k++) {
                int g = tid + k * NTH;           // float4 index
                int row = g >> 4, c4 = g & 15;
                *(float4*)(&s.Xs[row][c4 * 4]) = *(const float4*)(xt + row * NC + c4 * 4);
            }
        }
        __syncthreads();

        // ---- proj: K[i][d] = X[i][:].Wk[d][:] + b ----
        uint64_t acc[8][4];
        #pragma unroll
        for (int a = 0; a < 8; a++)
            #pragma unroll
            for (int e2 = 0; e2 < 4; e2++) acc[a][e2] = binit[e2];

        #pragma unroll 2
        for (int c4 = 0; c4 < 16; c4++) {
            float4 x4[8];
            #pragma unroll
            for (int a = 0; a < 8; a++) x4[a] = *(const float4*)(&s.Xs[i0 + a][c4 * 4]);
            #pragma unroll
            for (int k = 0; k < 4; k++) {
                const int c = c4 * 4 + k;
                ulonglong2 w01 = *(const ulonglong2*)(&s.Wt[c][j0]);
                ulonglong2 w23 = *(const ulonglong2*)(&s.Wt[c][j0 + 4]);
                #pragma unroll
                for (int a = 0; a < 8; a++) {
                    float xs = (k == 0) ? x4[a].x : (k == 1) ? x4[a].y : (k == 2) ? x4[a].z : x4[a].w;
                    uint64_t xd = pack2(xs, xs);
                    ffma2(acc[a][0], xd, w01.x);
                    ffma2(acc[a][1], xd, w01.y);
                    ffma2(acc[a][2], xd, w23.x);
                    ffma2(acc[a][3], xd, w23.y);
                }
            }
        }

        // ---- normalize (deterministic staged reduction) ----
        float f[8][8];
        #pragma unroll
        for (int a = 0; a < 8; a++) {
            float sq = 0.f;
            #pragma unroll
            for (int e2 = 0; e2 < 4; e2++) {
                float2 v = unpack2(acc[a][e2]);
                f[a][2 * e2] = v.x; f[a][2 * e2 + 1] = v.y;
                sq += v.x * v.x + v.y * v.y;
            }
            s.red[i0 + a][tj] = sq;
        }
        __syncthreads();
        {
            float sq = 0.f;
            #pragma unroll
            for (int j = 0; j < 8; j++) sq += s.red[tid][j];
            s.invn[tid] = rsqrtf(sq);
        }
        __syncthreads();
        {
            float kspart[8];
            #pragma unroll
            for (int e = 0; e < 8; e++) kspart[e] = 0.f;
            #pragma unroll
            for (int a = 0; a < 8; a++) {
                const float sc = s.invn[i0 + a];
                float kp[8];
                #pragma unroll
                for (int e = 0; e < 8; e++) { kp[e] = f[a][e] * sc; kspart[e] += kp[e]; }
                *(float4*)(&s.Ks[i0 + a][j0])     = make_float4(kp[0], kp[1], kp[2], kp[3]);
                *(float4*)(&s.Ks[i0 + a][j0 + 4]) = make_float4(kp[4], kp[5], kp[6], kp[7]);
            }
            #pragma unroll
            for (int e = 0; e < 8; e++) s.red2[j0 + e][ti] = kspart[e];
        }
        __syncthreads();
        if (tid < ND) {
            float v = 0.f;
            #pragma unroll
            for (int g = 0; g < 16; g++) v += s.red2[tid][g];
            s.ksum_s[tid] += v;
        }

        // ---- kv[d][c] += sum_i Kn[i][d] * X[i][c]  (halves split the i range) ----
        #pragma unroll 1
        for (int i = 0; i < 64; i++) {
            const int ii = half * 64 + i;
            float4 ka = *(const float4*)(&s.Ks[ii][d0]);
            float4 kb = *(const float4*)(&s.Ks[ii][d0 + 4]);
            ulonglong2 xv01 = *(const ulonglong2*)(&s.Xs[ii][c0]);
            ulonglong2 xv23 = *(const ulonglong2*)(&s.Xs[ii][c0 + 4]);
            float kd[8] = {ka.x, ka.y, ka.z, ka.w, kb.x, kb.y, kb.z, kb.w};
            #pragma unroll
            for (int a = 0; a < 8; a++) {
                uint64_t k2 = pack2(kd[a], kd[a]);
                ffma2(kvacc[a][0], k2, xv01.x);
                ffma2(kvacc[a][1], k2, xv01.y);
                ffma2(kvacc[a][2], k2, xv23.x);
                ffma2(kvacc[a][3], k2, xv23.y);
            }
        }
    }
    __syncthreads();

    // write partials
    {
        const int p = split * 2 + half;
        float* dst = g_kv_part + (((size_t)(b * NH + h) * NPART + p) * ND + d0) * NC + c0;
        #pragma unroll
        for (int a = 0; a < 8; a++) {
            float2 v0 = unpack2(kvacc[a][0]), v1 = unpack2(kvacc[a][1]);
            float2 v2 = unpack2(kvacc[a][2]), v3 = unpack2(kvacc[a][3]);
            *(float4*)(dst + a * NC)     = make_float4(v0.x, v0.y, v1.x, v1.y);
            *(float4*)(dst + a * NC + 4) = make_float4(v2.x, v2.y, v3.x, v3.y);
        }
    }
    if (tid < ND)
        g_ksum_part[((size_t)(b * NH + h) * SPLIT + split) * ND + tid] = s.ksum_s[tid];
}

// ---------------- reduce split partials ----------------
__global__ __launch_bounds__(256) void reduce_kernel() {
    const int KV = NB * NH * ND * NC;
    const int KS = NB * NH * ND;
    int idx = blockIdx.x * 256 + threadIdx.x;
    if (idx < KV) {
        int bh = idx / (ND * NC), rem = idx % (ND * NC);
        float sum = 0.f;
        #pragma unroll
        for (int sp = 0; sp < NPART; sp++)
            sum += g_kv_part[((size_t)bh * NPART + sp) * (ND * NC) + rem];
        g_kv[idx] = sum;
    } else if (idx < KV + KS) {
        int j = idx - KV;
        int bh = j / ND, rem = j % ND;
        float sum = 0.f;
        #pragma unroll
        for (int sp = 0; sp < SPLIT; sp++)
            sum += g_ksum_part[((size_t)bh * SPLIT + sp) * ND + rem];
        g_ksum[j] = sum;
    }
}

// ---------------- Q path + output ----------------
__global__ __launch_bounds__(NTH) void out_kernel(
    const float* __restrict__ x,
    const float* __restrict__ Wq_w,
    const float* __restrict__ Wq_b,
    const int* __restrict__ n_nodes,
    float* __restrict__ out)
{
    extern __shared__ char sraw[];
    SmemOut& s = *reinterpret_cast<SmemOut*>(sraw);
    const int t = blockIdx.x, b = blockIdx.y;
    const int tid = threadIdx.x;
    const int ti = tid >> 3, tj = tid & 7;
    const int i0 = ti * 8, j0 = tj * 8;
    const float nn = (float)n_nodes[b];

    // stage X tile + vsum (once per block)
    {
        const float* xt = x + (size_t)(b * NPG + t * TILE) * NC;
        #pragma unroll
        for (int k = 0; k < 16; k++) {
            int g = tid + k * NTH;
            int row = g >> 4, c4 = g & 15;
            *(float4*)(&s.Xs[row][c4 * 4]) = *(const float4*)(xt + row * NC + c4 * 4);
        }
        if (tid < NC) s.vsum[tid] = g_vsum[b * NC + tid];
    }

    for (int h = 0; h < NH; h++) {
        __syncthreads();  // protects Wt/kvs reuse + initial staging
        {
            const int d = tid & 63, cg = tid >> 6;
            const float* wrow = Wq_w + (size_t)(h * ND + d) * NC + cg * 32;
            #pragma unroll
            for (int k = 0; k < 8; k++) {
                float4 w4 = *(const float4*)(wrow + k * 4);
                int c = cg * 32 + k * 4;
                s.Wt[c + 0][d] = w4.x; s.Wt[c + 1][d] = w4.y;
                s.Wt[c + 2][d] = w4.z; s.Wt[c + 3][d] = w4.w;
            }
            const float4* kvsrc = (const float4*)(g_kv + (size_t)(b * NH + h) * (ND * NC));
            float4* kvdst = (float4*)(&s.kvs[0][0]);
            #pragma unroll
            for (int k = 0; k < 8; k++) kvdst[tid + k * NTH] = kvsrc[tid + k * NTH];
            if (tid < ND) {
                s.bqs[tid] = Wq_b[h * ND + tid];
                s.ksum[tid] = g_ksum[(size_t)(b * NH + h) * ND + tid];
            }
        }
        __syncthreads();

        // ---- GEMM1: Qraw = X.Wq^T + b ----
        uint64_t acc[8][4];
        {
            uint64_t binit[4];
            #pragma unroll
            for (int e2 = 0; e2 < 4; e2++)
                binit[e2] = pack2(s.bqs[j0 + 2 * e2], s.bqs[j0 + 2 * e2 + 1]);
            #pragma unroll
            for (int a = 0; a < 8; a++)
                #pragma unroll
                for (int e2 = 0; e2 < 4; e2++) acc[a][e2] = binit[e2];
        }
        #pragma unroll 2
        for (int c4 = 0; c4 < 16; c4++) {
            float4 x4[8];
            #pragma unroll
            for (int a = 0; a < 8; a++) x4[a] = *(const float4*)(&s.Xs[i0 + a][c4 * 4]);
            #pragma unroll
            for (int k = 0; k < 4; k++) {
                const int c = c4 * 4 + k;
                ulonglong2 w01 = *(const ulonglong2*)(&s.Wt[c][j0]);
                ulonglong2 w23 = *(const ulonglong2*)(&s.Wt[c][j0 + 4]);
                #pragma unroll
                for (int a = 0; a < 8; a++) {
                    float xs = (k == 0) ? x4[a].x : (k == 1) ? x4[a].y : (k == 2) ? x4[a].z : x4[a].w;
                    uint64_t xd = pack2(xs, xs);
                    ffma2(acc[a][0], xd, w01.x);
                    ffma2(acc[a][1], xd, w01.y);
                    ffma2(acc[a][2], xd, w23.x);
                    ffma2(acc[a][3], xd, w23.y);
                }
            }
        }

        // ---- reductions: sumsq(q), dot(q, ksum); store raw Q ----
        #pragma unroll
        for (int a = 0; a < 8; a++) {
            float f[8];
            float sq = 0.f, dk = 0.f;
            #pragma unroll
            for (int e2 = 0; e2 < 4; e2++) {
                float2 v = unpack2(acc[a][e2]);
                f[2 * e2] = v.x; f[2 * e2 + 1] = v.y;
            }
            #pragma unroll
            for (int e = 0; e < 8; e++) {
                sq += f[e] * f[e];
                dk += f[e] * s.ksum[j0 + e];
            }
            s.red1[i0 + a][tj] = sq;
            s.red2[i0 + a][tj] = dk;
            *(float4*)(&s.Qs[i0 + a][j0])     = make_float4(f[0], f[1], f[2], f[3]);
            *(float4*)(&s.Qs[i0 + a][j0 + 4]) = make_float4(f[4], f[5], f[6], f[7]);
        }
        __syncthreads();
        {
            float sq = 0.f, dk = 0.f;
            #pragma unroll
            for (int j = 0; j < 8; j++) { sq += s.red1[tid][j]; dk += s.red2[tid][j]; }
            float sc = rsqrtf(sq);
            s.scale[tid] = sc;
            s.invden[tid] = 1.0f / (sc * dk + nn);
        }
        __syncthreads();

        // ---- GEMM2: r = Qraw . kv ----
        uint64_t r2[8][4];
        #pragma unroll
        for (int a = 0; a < 8; a++)
            #pragma unroll
            for (int e2 = 0; e2 < 4; e2++) r2[a][e2] = 0ull;

        #pragma unroll 2
        for (int d4 = 0; d4 < 16; d4++) {
            float4 q4[8];
            #pragma unroll
            for (int a = 0; a < 8; a++) q4[a] = *(const float4*)(&s.Qs[i0 + a][d4 * 4]);
            #pragma unroll
            for (int k = 0; k < 4; k++) {
                const int d = d4 * 4 + k;
                ulonglong2 kv01 = *(const ulonglong2*)(&s.kvs[d][j0]);
                ulonglong2 kv23 = *(const ulonglong2*)(&s.kvs[d][j0 + 4]);
                #pragma unroll
                for (int a = 0; a < 8; a++) {
                    float qs = (k == 0) ? q4[a].x : (k == 1) ? q4[a].y : (k == 2) ? q4[a].z : q4[a].w;
                    uint64_t qd = pack2(qs, qs);
                    ffma2(r2[a][0], qd, kv01.x);
                    ffma2(r2[a][1], qd, kv01.y);
                    ffma2(r2[a][2], qd, kv23.x);
                    ffma2(r2[a][3], qd, kv23.y);
                }
            }
        }

        // ---- epilogue ----
        #pragma unroll
        for (int a = 0; a < 8; a++) {
            const float sc  = s.scale[i0 + a];
            const float idn = s.invden[i0 + a];
            float2 v0 = unpack2(r2[a][0]), v1 = unpack2(r2[a][1]);
            float2 v2 = unpack2(r2[a][2]), v3 = unpack2(r2[a][3]);
            float rr[8] = {v0.x, v0.y, v1.x, v1.y, v2.x, v2.y, v3.x, v3.y};
            float o[8];
            #pragma unroll
            for (int e = 0; e < 8; e++)
                o[e] = (sc * rr[e] + s.vsum[j0 + e]) * idn;
            float* orow = out + (size_t)(b * NPG + t * TILE + i0 + a) * (NH * NC) + h * NC + j0;
            *(float4*)(orow)     = make_float4(o[0], o[1], o[2], o[3]);
            *(float4*)(orow + 4) = make_float4(o[4], o[5], o[6], o[7]);
        }
    }
}

// ---------------- launch ----------------
extern "C" void kernel_launch(void* const* d_in, const int* in_sizes, int n_in,
                              void* d_out, int out_size) {
    const float* x    = (const float*)d_in[0];
    const float* Wq_w = (const float*)d_in[1];
    const float* Wq_b = (const float*)d_in[2];
    const float* Wk_w = (const float*)d_in[3];
    const float* Wk_b = (const float*)d_in[4];
    const int*   n_nodes = (const int*)d_in[5];
    float* out = (float*)d_out;

    cudaFuncSetAttribute(kv_kernel, cudaFuncAttributeMaxDynamicSharedMemorySize,
                         (int)sizeof(SmemKV));
    cudaFuncSetAttribute(out_kernel, cudaFuncAttributeMaxDynamicSharedMemorySize,
                         (int)sizeof(SmemOut));

    vsum_kernel<<<NB, 256>>>(x);
    kv_kernel<<<dim3(SPLIT, NH, NB), NTH, sizeof(SmemKV)>>>(x, Wk_w, Wk_b);

    const int total = NB * NH * ND * NC + NB * NH * ND;
    reduce_kernel<<<(total + 255) / 256, 256>>>();

    out_kernel<<<dim3(NPG / TILE, NB), NTH, sizeof(SmemOut)>>>(x, Wq_w, Wq_b, n_nodes, out);
}